// round 1
// baseline (speedup 1.0000x reference)
#include <cuda_runtime.h>
#include <math.h>
#include <float.h>

#define NN 100000
#define EE 3200000
#define IND 64
#define HID 128
#define NCLS 10

// ---------------- scratch (device globals; no runtime allocation) ----------
__device__ float d_A1[(size_t)NN * IND];   // adj @ x                [N,64]
__device__ float d_h1[(size_t)NN * HID];   // relu(A1@W1 + rs*b1)    [N,128]
__device__ float d_A2[(size_t)NN * HID];   // adj @ h1               [N,128]
__device__ float d_h [(size_t)NN * HID];   // h1 + relu(A2@W2+rs*b2) [N,128]
__device__ float d_s [NN];                 // attention scores
__device__ float d_rowsum[NN];             // adj @ 1
__device__ int   d_rowptr[NN + 1];
__device__ float d_g[HID];
__device__ float d_Z;
__device__ float d_max;

// ---------------- helpers ---------------------------------------------------
__device__ __forceinline__ void atomicMaxFloat(float* addr, float val) {
    int* ia = (int*)addr;
    int old = *ia;
    while (__int_as_float(old) < val) {
        int assumed = old;
        old = atomicCAS(ia, assumed, __float_as_int(val));
        if (old == assumed) break;
    }
}

// ---------------- kernel 0: row_ptr build + accumulator init ---------------
__global__ void k_init(const int* __restrict__ erows) {
    int i = blockIdx.x * blockDim.x + threadIdx.x;
    if (i < HID) d_g[i] = 0.f;
    if (i == HID)     d_Z = 0.f;
    if (i == HID + 1) d_max = -FLT_MAX;
    if (i > NN) return;
    if (i == NN) { d_rowptr[NN] = EE; return; }
    // lower_bound: first e with erows[e] >= i
    int lo = 0, hi = EE;
    while (lo < hi) {
        int mid = (lo + hi) >> 1;
        if (erows[mid] < i) lo = mid + 1; else hi = mid;
    }
    d_rowptr[i] = lo;
}

// ---------------- kernel 1: A1 = adj @ x (64 dims) + rowsum -----------------
__global__ void k_spmm64(const float* __restrict__ mat,
                         const int* __restrict__ cols,
                         const float* __restrict__ vals) {
    int row = blockIdx.x * 8 + (threadIdx.x >> 5);
    if (row >= NN) return;
    int lane = threadIdx.x & 31;
    int s = d_rowptr[row], e = d_rowptr[row + 1];
    float2 acc = make_float2(0.f, 0.f);
    float vs = 0.f;
    const float2* m2 = (const float2*)mat;
    for (int i = s; i < e; i++) {
        float v = __ldg(vals + i);       // warp-broadcast
        int   c = __ldg(cols + i);       // warp-broadcast
        float2 xv = m2[(size_t)c * 32 + lane];
        acc.x += v * xv.x;
        acc.y += v * xv.y;
        vs += v;
    }
    ((float2*)d_A1)[(size_t)row * 32 + lane] = acc;
    if (lane == 0) d_rowsum[row] = vs;
}

// ---------------- kernel 3: A2 = adj @ h1 (128 dims) ------------------------
__global__ void k_spmm128(const int* __restrict__ cols,
                          const float* __restrict__ vals) {
    int row = blockIdx.x * 8 + (threadIdx.x >> 5);
    if (row >= NN) return;
    int lane = threadIdx.x & 31;
    int s = d_rowptr[row], e = d_rowptr[row + 1];
    float4 acc = make_float4(0.f, 0.f, 0.f, 0.f);
    const float4* m4 = (const float4*)d_h1;
    for (int i = s; i < e; i++) {
        float v = __ldg(vals + i);
        int   c = __ldg(cols + i);
        float4 xv = m4[(size_t)c * 32 + lane];
        acc.x += v * xv.x;
        acc.y += v * xv.y;
        acc.z += v * xv.z;
        acc.w += v * xv.w;
    }
    ((float4*)d_A2)[(size_t)row * 32 + lane] = acc;
}

// ---------------- GEMM: C[N,128] = epilogue(A[N,K] @ W[K,128]) --------------
// BM=64, BN=128, BK=16, 256 threads, 8x4 micro-tile per thread.
// EPI==0: C = relu(acc + rowsum*b)           (h1)
// EPI==1: C = Hprev + relu(acc + rowsum*b)   (h = h1 + h2)
template <int K, int EPI>
__global__ void k_gemm(const float* __restrict__ A,
                       const float* __restrict__ W,
                       const float* __restrict__ b,
                       float* __restrict__ C,
                       const float* __restrict__ Hprev) {
    __shared__ float A_sh[64][16];
    __shared__ float W_sh[16][128];
    int tid = threadIdx.x;
    int tx = tid & 31, ty = tid >> 5;
    int row0 = blockIdx.x * 64;

    float acc[8][4];
#pragma unroll
    for (int r = 0; r < 8; r++)
#pragma unroll
        for (int j = 0; j < 4; j++) acc[r][j] = 0.f;

    for (int k0 = 0; k0 < K; k0 += 16) {
        // A tile: 64x16, one float4 per thread
        {
            int r = tid >> 2, c4 = (tid & 3) * 4;
            int gr = row0 + r;
            float4 v = make_float4(0.f, 0.f, 0.f, 0.f);
            if (gr < NN) v = *(const float4*)(A + (size_t)gr * K + k0 + c4);
            *(float4*)&A_sh[r][c4] = v;
        }
        // W tile: 16x128, two float4 per thread
        {
            int base = tid * 8;
            int wr = base >> 7, wc = base & 127;
            *(float4*)&W_sh[wr][wc]     = *(const float4*)(W + (size_t)(k0 + wr) * 128 + wc);
            *(float4*)&W_sh[wr][wc + 4] = *(const float4*)(W + (size_t)(k0 + wr) * 128 + wc + 4);
        }
        __syncthreads();
#pragma unroll
        for (int kk = 0; kk < 16; kk++) {
            float4 w = *(float4*)&W_sh[kk][tx * 4];
#pragma unroll
            for (int r = 0; r < 8; r++) {
                float a = A_sh[ty * 8 + r][kk];
                acc[r][0] += a * w.x;
                acc[r][1] += a * w.y;
                acc[r][2] += a * w.z;
                acc[r][3] += a * w.w;
            }
        }
        __syncthreads();
    }

    float4 bb = *(const float4*)(b + tx * 4);
#pragma unroll
    for (int r = 0; r < 8; r++) {
        int gr = row0 + ty * 8 + r;
        if (gr >= NN) continue;
        float rs = d_rowsum[gr];
        float4 o;
        o.x = fmaxf(acc[r][0] + rs * bb.x, 0.f);
        o.y = fmaxf(acc[r][1] + rs * bb.y, 0.f);
        o.z = fmaxf(acc[r][2] + rs * bb.z, 0.f);
        o.w = fmaxf(acc[r][3] + rs * bb.w, 0.f);
        if (EPI == 1) {
            float4 hp = *(const float4*)(Hprev + (size_t)gr * 128 + tx * 4);
            o.x += hp.x; o.y += hp.y; o.z += hp.z; o.w += hp.w;
        }
        *(float4*)(C + (size_t)gr * 128 + tx * 4) = o;
    }
}

// ---------------- kernel 5: scores + global max ------------------------------
__global__ void k_score(const float* __restrict__ att_w,
                        const float* __restrict__ att_b) {
    __shared__ float aw[128];
    __shared__ float wmax[8];
    int tid = threadIdx.x;
    if (tid < 128) aw[tid] = att_w[tid];
    __syncthreads();
    int lane = tid & 31, wid = tid >> 5;
    int nwarps = gridDim.x * (blockDim.x >> 5);
    int gw = blockIdx.x * (blockDim.x >> 5) + wid;
    float ab = att_b[0];
    float local_max = -FLT_MAX;
    const float4* h4 = (const float4*)d_h;
    const float4* a4 = (const float4*)aw;
    for (int row = gw; row < NN; row += nwarps) {
        float4 h = h4[(size_t)row * 32 + lane];
        float4 a = a4[lane];
        float d = h.x * a.x + h.y * a.y + h.z * a.z + h.w * a.w;
#pragma unroll
        for (int o = 16; o; o >>= 1) d += __shfl_xor_sync(0xFFFFFFFFu, d, o);
        d += ab;
        if (lane == 0) d_s[row] = d;
        local_max = fmaxf(local_max, d);
    }
    if (lane == 0) wmax[wid] = local_max;
    __syncthreads();
    if (tid == 0) {
        float m = wmax[0];
        for (int i = 1; i < (int)(blockDim.x >> 5); i++) m = fmaxf(m, wmax[i]);
        atomicMaxFloat(&d_max, m);
    }
}

// ---------------- kernel 6: Z and g = sum exp(s-m)*h -------------------------
__global__ void k_weighted() {
    __shared__ float gsh[128];
    __shared__ float zsh;
    int tid = threadIdx.x, lane = tid & 31, wid = tid >> 5;
    if (tid < 128) gsh[tid] = 0.f;
    if (tid == 128) zsh = 0.f;
    __syncthreads();
    int nwarps = gridDim.x * (blockDim.x >> 5);
    int gw = blockIdx.x * (blockDim.x >> 5) + wid;
    float m = d_max;
    float4 acc = make_float4(0.f, 0.f, 0.f, 0.f);
    float zacc = 0.f;
    const float4* h4 = (const float4*)d_h;
    for (int row = gw; row < NN; row += nwarps) {
        float e = expf(d_s[row] - m);
        float4 h = h4[(size_t)row * 32 + lane];
        acc.x += e * h.x;
        acc.y += e * h.y;
        acc.z += e * h.z;
        acc.w += e * h.w;
        if (lane == 0) zacc += e;
    }
    atomicAdd(&gsh[lane * 4 + 0], acc.x);
    atomicAdd(&gsh[lane * 4 + 1], acc.y);
    atomicAdd(&gsh[lane * 4 + 2], acc.z);
    atomicAdd(&gsh[lane * 4 + 3], acc.w);
    if (lane == 0) atomicAdd(&zsh, zacc);
    __syncthreads();
    if (tid < 128) atomicAdd(&d_g[tid], gsh[tid]);
    if (tid == 128) atomicAdd(&d_Z, zsh);
}

// ---------------- kernel 7: out = (g/Z) @ cls_w + cls_b ----------------------
__global__ void k_final(const float* __restrict__ cls_w,
                        const float* __restrict__ cls_b,
                        float* __restrict__ out) {
    int c = threadIdx.x;
    if (c < NCLS) {
        float invZ = 1.f / d_Z;
        float acc = cls_b[c];
        for (int k = 0; k < HID; k++)
            acc += (d_g[k] * invZ) * cls_w[k * NCLS + c];
        out[c] = acc;
    }
}

// ---------------- launch ------------------------------------------------------
extern "C" void kernel_launch(void* const* d_in, const int* in_sizes, int n_in,
                              void* d_out, int out_size) {
    const float* x     = (const float*)d_in[0];
    const int*   erows = (const int*)  d_in[1];
    const int*   ecols = (const int*)  d_in[2];
    const float* evals = (const float*)d_in[3];
    const float* fc1_w = (const float*)d_in[4];
    const float* fc1_b = (const float*)d_in[5];
    const float* fc2_w = (const float*)d_in[6];
    const float* fc2_b = (const float*)d_in[7];
    const float* att_w = (const float*)d_in[8];
    const float* att_b = (const float*)d_in[9];
    const float* cls_w = (const float*)d_in[10];
    const float* cls_b = (const float*)d_in[11];
    float* out = (float*)d_out;

    float* pA1 = nullptr; float* pH1 = nullptr; float* pA2 = nullptr; float* pH = nullptr;
    cudaGetSymbolAddress((void**)&pA1, d_A1);
    cudaGetSymbolAddress((void**)&pH1, d_h1);
    cudaGetSymbolAddress((void**)&pA2, d_A2);
    cudaGetSymbolAddress((void**)&pH,  d_h);

    k_init<<<(NN + 1 + 255) / 256, 256>>>(erows);
    k_spmm64<<<(NN + 7) / 8, 256>>>(x, ecols, evals);
    k_gemm<IND, 0><<<(NN + 63) / 64, 256>>>(pA1, fc1_w, fc1_b, pH1, nullptr);
    k_spmm128<<<(NN + 7) / 8, 256>>>(ecols, evals);
    k_gemm<HID, 1><<<(NN + 63) / 64, 256>>>(pA2, fc2_w, fc2_b, pH, pH1);
    k_score<<<1184, 256>>>(att_w, att_b);
    k_weighted<<<1184, 256>>>();
    k_final<<<1, 32>>>(cls_w, cls_b, out);
}